// round 1
// baseline (speedup 1.0000x reference)
#include <cuda_runtime.h>
#include <math.h>

#define B_ 16
#define N_ 2304
#define D_ 1024
#define H_ 1344
#define W_ 1344
#define M_ 8
#define HV_ 48
#define PH_ 28
#define NRAYS 24
#define NSAMP 20
#define NCHUNK 18          // 2304 / 128
#define CHUNK_N 128

// ---------------- scratch (static device globals; no allocations) ----------------
__device__ unsigned char g_packed[H_ * W_];                 // 8 masks bitpacked per pixel
__device__ int           g_patchsum[M_ * N_];               // per-mask per-patch popcount
__device__ float         g_soft2d[M_ * N_];
__device__ float         g_logsoft[M_ * N_];
__device__ float         g_msc[M_ * 8];                     // 0:count 1:cx 2:cy 3:cx_pix 4:cy_pix
__device__ float         g_scores[B_ * N_];
__device__ float         g_weights[M_ * B_ * N_];
__device__ float         g_rowd[M_ * B_ * H_];
__device__ float         g_rowd2[M_ * B_ * H_];
__device__ float         g_partial[NCHUNK * M_ * B_ * D_];  // 9.4 MB

// ---------------- reduction helpers ----------------
__device__ __forceinline__ float blockSum(float v, float* sm) {
    int lane = threadIdx.x & 31, w = threadIdx.x >> 5;
    int nw = blockDim.x >> 5;
#pragma unroll
    for (int o = 16; o; o >>= 1) v += __shfl_down_sync(0xffffffffu, v, o);
    if (lane == 0) sm[w] = v;
    __syncthreads();
    if (w == 0) {
        v = (lane < nw) ? sm[lane] : 0.f;
#pragma unroll
        for (int o = 16; o; o >>= 1) v += __shfl_down_sync(0xffffffffu, v, o);
        if (lane == 0) sm[0] = v;
    }
    __syncthreads();
    float r = sm[0];
    __syncthreads();
    return r;
}

__device__ __forceinline__ float blockMax(float v, float* sm) {
    int lane = threadIdx.x & 31, w = threadIdx.x >> 5;
    int nw = blockDim.x >> 5;
#pragma unroll
    for (int o = 16; o; o >>= 1) v = fmaxf(v, __shfl_down_sync(0xffffffffu, v, o));
    if (lane == 0) sm[w] = v;
    __syncthreads();
    if (w == 0) {
        v = (lane < nw) ? sm[lane] : -1e30f;
#pragma unroll
        for (int o = 16; o; o >>= 1) v = fmaxf(v, __shfl_down_sync(0xffffffffu, v, o));
        if (lane == 0) sm[0] = v;
    }
    __syncthreads();
    float r = sm[0];
    __syncthreads();
    return r;
}

// ---------------- K1: scores[b,n] = tokens[b,n,:] . gate_w ----------------
__global__ void k1_scores(const float* __restrict__ tok, const float* __restrict__ gw) {
    int warp = (blockIdx.x * blockDim.x + threadIdx.x) >> 5;
    int lane = threadIdx.x & 31;
    if (warp >= B_ * N_) return;
    const float4* t = (const float4*)(tok + (size_t)warp * D_);
    const float4* g = (const float4*)gw;
    float acc = 0.f;
#pragma unroll
    for (int i = 0; i < 8; i++) {
        float4 a = t[lane + i * 32];
        float4 w = g[lane + i * 32];
        acc += a.x * w.x + a.y * w.y + a.z * w.z + a.w * w.w;
    }
#pragma unroll
    for (int o = 16; o; o >>= 1) acc += __shfl_down_sync(0xffffffffu, acc, o);
    if (lane == 0) g_scores[warp] = acc;
}

// ---------------- K2: mask pass: bitpack + per-patch sums ----------------
__global__ void k2_mask(const int* __restrict__ masks) {
    int p = blockIdx.x;             // 0..2303
    int py = p / HV_, px = p % HV_;
    int tid = threadIdx.x;          // 256
    int sums[M_];
#pragma unroll
    for (int m = 0; m < M_; m++) sums[m] = 0;

    if (tid < 196) {                // 28 rows * 7 int4-groups
        int row = tid / 7, g = tid % 7;
        int y = py * PH_ + row;
        int x = px * PH_ + g * 4;
        unsigned b0 = 0, b1 = 0, b2 = 0, b3 = 0;
#pragma unroll
        for (int m = 0; m < M_; m++) {
            int4 v = *(const int4*)(masks + ((size_t)m * H_ + y) * W_ + x);
            int q0 = (v.x != 0), q1 = (v.y != 0), q2 = (v.z != 0), q3 = (v.w != 0);
            sums[m] = q0 + q1 + q2 + q3;
            b0 |= (unsigned)q0 << m; b1 |= (unsigned)q1 << m;
            b2 |= (unsigned)q2 << m; b3 |= (unsigned)q3 << m;
        }
        *(uchar4*)(g_packed + (size_t)y * W_ + x) =
            make_uchar4((unsigned char)b0, (unsigned char)b1, (unsigned char)b2, (unsigned char)b3);
    }

    __shared__ int ssum[8 * M_];
    int lane = tid & 31, w = tid >> 5;
#pragma unroll
    for (int m = 0; m < M_; m++) {
        int v = sums[m];
#pragma unroll
        for (int o = 16; o; o >>= 1) v += __shfl_down_sync(0xffffffffu, v, o);
        if (lane == 0) ssum[w * M_ + m] = v;
    }
    __syncthreads();
    if (tid < M_) {
        int t = 0;
#pragma unroll
        for (int ww = 0; ww < 8; ww++) t += ssum[ww * M_ + tid];
        g_patchsum[tid * N_ + p] = t;
    }
}

// ---------------- K2b: per-mask soft2d / logsoft / scalars ----------------
__global__ void k2b_scalars() {
    int m = blockIdx.x;
    int tid = threadIdx.x;  // 256
    __shared__ float sm[32];
    float c = 0.f, ss = 0.f, sx = 0.f, sy = 0.f;
    for (int p = tid; p < N_; p += 256) {
        int ps = g_patchsum[m * N_ + p];
        float cov = (float)ps * (1.f / 784.f);
        float soft = 1.f / (1.f + expf(-50.f * (cov - 0.3f)));
        g_soft2d[m * N_ + p] = soft;
        g_logsoft[m * N_ + p] = logf(fmaxf(soft, 1e-8f));
        c += (float)ps;
        ss += soft;
        sx += soft * (float)(p % HV_);
        sy += soft * (float)(p / HV_);
    }
    c  = blockSum(c, sm);
    ss = blockSum(ss, sm);
    sx = blockSum(sx, sm);
    sy = blockSum(sy, sm);
    if (tid == 0) {
        float soft_sum = ss + 1e-8f;
        float cx = sx / (soft_sum * (float)HV_);
        float cy = sy / (soft_sum * (float)HV_);
        g_msc[m * 8 + 0] = c;
        g_msc[m * 8 + 1] = cx;
        g_msc[m * 8 + 2] = cy;
        g_msc[m * 8 + 3] = cx * (float)(W_ - 1);
        g_msc[m * 8 + 4] = cy * (float)(H_ - 1);
    }
}

// ---------------- K3: depth row partials per (row, b) for all masks ----------------
__global__ void k3_depth(const float* __restrict__ depth) {
    int row = blockIdx.x, b = blockIdx.y;
    int tid = threadIdx.x;  // 256
    float a[M_], a2[M_];
#pragma unroll
    for (int m = 0; m < M_; m++) { a[m] = 0.f; a2[m] = 0.f; }
    const float* dr = depth + ((size_t)b * H_ + row) * W_;
    const unsigned char* pr = g_packed + (size_t)row * W_;
    for (int x = tid; x < W_; x += 256) {
        float d = dr[x];
        float dd = d * d;
        unsigned pb = pr[x];
#pragma unroll
        for (int m = 0; m < M_; m++) {
            float f = (float)((pb >> m) & 1u);
            a[m]  = fmaf(f, d,  a[m]);
            a2[m] = fmaf(f, dd, a2[m]);
        }
    }
    __shared__ float sred[8 * 16];
    int lane = tid & 31, w = tid >> 5;
#pragma unroll
    for (int i = 0; i < 16; i++) {
        float v = (i < 8) ? a[i] : a2[i - 8];
#pragma unroll
        for (int o = 16; o; o >>= 1) v += __shfl_down_sync(0xffffffffu, v, o);
        if (lane == 0) sred[w * 16 + i] = v;
    }
    __syncthreads();
    if (tid < 16) {
        float t = 0.f;
#pragma unroll
        for (int ww = 0; ww < 8; ww++) t += sred[ww * 16 + tid];
        if (tid < 8) g_rowd[((size_t)tid * B_ + b) * H_ + row] = t;
        else         g_rowd2[((size_t)(tid - 8) * B_ + b) * H_ + row] = t;
    }
}

// ---------------- K4: softmax weights per (m,b) ----------------
__global__ void k4_softmax() {
    int b = blockIdx.x, m = blockIdx.y;
    int tid = threadIdx.x;  // 256
    __shared__ float sm[32];
    __shared__ float buf[N_];
    float mx = -1e30f;
    for (int n = tid; n < N_; n += 256) {
        float v = g_scores[b * N_ + n] + g_logsoft[m * N_ + n];
        buf[n] = v;
        mx = fmaxf(mx, v);
    }
    __syncthreads();
    mx = blockMax(mx, sm);
    float s = 0.f;
    for (int n = tid; n < N_; n += 256) {
        float e = expf(buf[n] - mx);
        buf[n] = e;
        s += e;
    }
    __syncthreads();
    s = blockSum(s, sm);
    float inv = 1.f / s;
    for (int n = tid; n < N_; n += 256)
        g_weights[((size_t)m * B_ + b) * N_ + n] = buf[n] * inv;
}

// ---------------- K5: rgb partials: one token pass, all 8 masks ----------------
__global__ void k5_rgb_partial(const float* __restrict__ tok) {
    int chunk = blockIdx.x, b = blockIdx.y;
    int tid = threadIdx.x;  // 256 (thread owns 4 consecutive d via float4)
    __shared__ float wsm[M_ * CHUNK_N];
    for (int i = tid; i < M_ * CHUNK_N; i += 256) {
        int m = i >> 7, j = i & 127;
        wsm[i] = g_weights[((size_t)m * B_ + b) * N_ + chunk * CHUNK_N + j];
    }
    __syncthreads();
    float acc[M_][4];
#pragma unroll
    for (int m = 0; m < M_; m++)
#pragma unroll
        for (int k = 0; k < 4; k++) acc[m][k] = 0.f;

    const float4* tp = (const float4*)(tok + ((size_t)b * N_ + chunk * CHUNK_N) * D_) + tid;
    for (int j = 0; j < CHUNK_N; j++) {
        float4 t = tp[(size_t)j * (D_ / 4)];
#pragma unroll
        for (int m = 0; m < M_; m++) {
            float w = wsm[m * CHUNK_N + j];
            acc[m][0] = fmaf(w, t.x, acc[m][0]);
            acc[m][1] = fmaf(w, t.y, acc[m][1]);
            acc[m][2] = fmaf(w, t.z, acc[m][2]);
            acc[m][3] = fmaf(w, t.w, acc[m][3]);
        }
    }
#pragma unroll
    for (int m = 0; m < M_; m++) {
        *(float4*)&g_partial[(((size_t)chunk * M_ + m) * B_ + b) * D_ + tid * 4] =
            make_float4(acc[m][0], acc[m][1], acc[m][2], acc[m][3]);
    }
}

// ---------------- K6: reduce rgb partials -> out[0 : M*B*D] ----------------
__global__ void k6_rgb_reduce(float* __restrict__ out) {
    int idx = blockIdx.x * blockDim.x + threadIdx.x;
    if (idx >= M_ * B_ * D_) return;
    float s = 0.f;
#pragma unroll
    for (int c = 0; c < NCHUNK; c++) s += g_partial[(size_t)c * (M_ * B_ * D_) + idx];
    out[idx] = s;
}

// ---------------- bilinear helpers ----------------
__device__ __forceinline__ float bilin_border(const float* img, float x, float y) {
    x = fminf(fmaxf(x, 0.f), (float)(W_ - 1));
    y = fminf(fmaxf(y, 0.f), (float)(H_ - 1));
    float x0f = floorf(x), y0f = floorf(y);
    float wx = x - x0f, wy = y - y0f;
    int x0 = (int)x0f, y0 = (int)y0f;
    int x1 = min(x0 + 1, W_ - 1), y1 = min(y0 + 1, H_ - 1);
    return img[y0 * W_ + x0] * (1.f - wx) * (1.f - wy)
         + img[y0 * W_ + x1] * wx * (1.f - wy)
         + img[y1 * W_ + x0] * (1.f - wx) * wy
         + img[y1 * W_ + x1] * wx * wy;
}

__device__ __forceinline__ float tap48(const float* img, int yy, int xx, float w) {
    if (xx >= 0 && xx < HV_ && yy >= 0 && yy < HV_) return img[yy * HV_ + xx] * w;
    return 0.f;
}

__device__ __forceinline__ float bilin_zeros48(const float* img, float x, float y) {
    float x0f = floorf(x), y0f = floorf(y);
    float wx = x - x0f, wy = y - y0f;
    int x0 = (int)x0f, y0 = (int)y0f;
    float v = tap48(img, y0, x0, (1.f - wx) * (1.f - wy));
    v += tap48(img, y0, x0 + 1, wx * (1.f - wy));
    v += tap48(img, y0 + 1, x0, (1.f - wx) * wy);
    v += tap48(img, y0 + 1, x0 + 1, wx * wy);
    return v;
}

// ---------------- K7: rays + stats + GEMV + layernorm -> dep output ----------------
__global__ void k7_dep(const float* __restrict__ depth,
                       const float* __restrict__ dw, const float* __restrict__ db,
                       const float* __restrict__ gamma, const float* __restrict__ beta,
                       float* __restrict__ out) {
    int b = blockIdx.x, m = blockIdx.y;
    int tid = threadIdx.x;  // 512
    __shared__ float sm[32];
    __shared__ float s_stats[28];
    __shared__ float s_ds[NRAYS * NSAMP];
    __shared__ float s_sw[NRAYS * NSAMP];

    // 1. reduce depth row partials
    float a = 0.f, a2 = 0.f;
    for (int r = tid; r < H_; r += 512) {
        a  += g_rowd[((size_t)m * B_ + b) * H_ + r];
        a2 += g_rowd2[((size_t)m * B_ + b) * H_ + r];
    }
    float sum_d  = blockSum(a, sm);
    float sum_d2 = blockSum(a2, sm);

    float count = g_msc[m * 8 + 0];
    float cx    = g_msc[m * 8 + 1];
    float cy    = g_msc[m * 8 + 2];
    float cxp   = g_msc[m * 8 + 3];
    float cyp   = g_msc[m * 8 + 4];

    float mean_d = sum_d / fmaxf(count, 1.f);
    float var = (sum_d2 - count * mean_d * mean_d) / fmaxf(count - 1.f, 1.f);
    float std_d = (count > 1.f) ? sqrtf(fmaxf(var, 0.f)) : 0.f;

    // 2. ray sampling (480 points)
    if (tid < NRAYS * NSAMP) {
        int r = tid / NSAMP, s = tid % NSAMP;
        double ang = (2.0 * 3.14159265358979323846 / (double)NRAYS) * (double)r;
        float ca = (float)cos(ang), sa = (float)sin(ang);
        float tv = (float)(((double)(W_ < H_ ? W_ : H_) * 0.45 / (double)(NSAMP - 1)) * (double)s);
        float x = cxp + ca * tv;
        float y = cyp + sa * tv;
        const float* dm = depth + (size_t)b * H_ * W_;
        s_ds[tid] = bilin_border(dm, x, y);
        float xp = x / (float)(W_ - 1) * (float)(HV_ - 1);
        float yp = y / (float)(H_ - 1) * (float)(HV_ - 1);
        float sw = bilin_zeros48(g_soft2d + m * N_, xp, yp);
        s_sw[tid] = fmaxf(sw, 1e-6f);
    }
    __syncthreads();

    // 3. per-ray profile
    if (tid < NRAYS) {
        float ws = 0.f, pr = 0.f;
#pragma unroll
        for (int s = 0; s < NSAMP; s++) {
            ws += s_sw[tid * NSAMP + s];
            pr += s_ds[tid * NSAMP + s] * s_sw[tid * NSAMP + s];
        }
        float ok = (count > 0.f) ? 1.f : 0.f;
        s_stats[4 + tid] = (pr / ws) * ok;
    }
    if (tid == 0) {
        float ok = (count > 0.f) ? 1.f : 0.f;
        s_stats[0] = mean_d * ok;
        s_stats[1] = std_d * ok;
        s_stats[2] = cx * ok;
        s_stats[3] = cy * ok;
    }
    __syncthreads();

    // 4. h = stats @ depth_w + depth_b ; layernorm
    float h0 = db[tid], h1 = db[tid + 512];
#pragma unroll
    for (int k = 0; k < 28; k++) {
        float st = s_stats[k];
        h0 = fmaf(st, dw[k * D_ + tid], h0);
        h1 = fmaf(st, dw[k * D_ + tid + 512], h1);
    }
    float mu = blockSum(h0 + h1, sm) * (1.f / (float)D_);
    float e0 = h0 - mu, e1 = h1 - mu;
    float v2 = blockSum(e0 * e0 + e1 * e1, sm) * (1.f / (float)D_);
    float inv = rsqrtf(v2 + 1e-5f);
    size_t off = (size_t)(M_ * B_ * D_) + ((size_t)m * B_ + b) * D_;
    out[off + tid]       = e0 * inv * gamma[tid] + beta[tid];
    out[off + tid + 512] = e1 * inv * gamma[tid + 512] + beta[tid + 512];
}

// ---------------- launch ----------------
extern "C" void kernel_launch(void* const* d_in, const int* in_sizes, int n_in,
                              void* d_out, int out_size) {
    const float* tok   = (const float*)d_in[0];
    const float* depth = (const float*)d_in[1];
    const int*   masks = (const int*)d_in[2];
    const float* gw    = (const float*)d_in[3];
    const float* dw    = (const float*)d_in[4];
    const float* db    = (const float*)d_in[5];
    const float* gamma = (const float*)d_in[6];
    const float* beta  = (const float*)d_in[7];
    float* out = (float*)d_out;

    k1_scores<<<(B_ * N_ * 32 + 255) / 256, 256>>>(tok, gw);
    k2_mask<<<N_, 256>>>(masks);
    k2b_scalars<<<M_, 256>>>();
    k3_depth<<<dim3(H_, B_), 256>>>(depth);
    k4_softmax<<<dim3(B_, M_), 256>>>();
    k5_rgb_partial<<<dim3(NCHUNK, B_), 256>>>(tok);
    k6_rgb_reduce<<<(M_ * B_ * D_ + 255) / 256, 256>>>(out);
    k7_dep<<<dim3(B_, M_), 512>>>(depth, dw, db, gamma, beta, out);
}

// round 2
// speedup vs baseline: 1.2526x; 1.2526x over previous
#include <cuda_runtime.h>
#include <math.h>

#define B_ 16
#define N_ 2304
#define D_ 1024
#define H_ 1344
#define W_ 1344
#define M_ 8
#define HV_ 48
#define PH_ 28
#define NRAYS 24
#define NSAMP 20
#define NCHUNK 36          // 2304 / 64
#define CHUNK_N 64

// ---------------- scratch (static device globals; no allocations) ----------------
__device__ unsigned char g_packed[H_ * W_];                 // 8 masks bitpacked per pixel
__device__ int           g_patchsum[M_ * N_];
__device__ float         g_soft2d[M_ * N_];
__device__ float         g_logsoft[M_ * N_];
__device__ float         g_msc[M_ * 8];                     // 0:count 1:cx 2:cy 3:cx_pix 4:cy_pix
__device__ float         g_rowd[M_ * B_ * H_];
__device__ float         g_rowd2[M_ * B_ * H_];
__device__ float         g_partial[NCHUNK * M_ * B_ * D_];  // 18.9 MB
__device__ float         g_locmax[NCHUNK * M_ * B_];
__device__ float         g_locsum[NCHUNK * M_ * B_];

// ---------------- reduction helpers ----------------
__device__ __forceinline__ float blockSum(float v, float* sm) {
    int lane = threadIdx.x & 31, w = threadIdx.x >> 5;
    int nw = blockDim.x >> 5;
#pragma unroll
    for (int o = 16; o; o >>= 1) v += __shfl_down_sync(0xffffffffu, v, o);
    if (lane == 0) sm[w] = v;
    __syncthreads();
    if (w == 0) {
        v = (lane < nw) ? sm[lane] : 0.f;
#pragma unroll
        for (int o = 16; o; o >>= 1) v += __shfl_down_sync(0xffffffffu, v, o);
        if (lane == 0) sm[0] = v;
    }
    __syncthreads();
    float r = sm[0];
    __syncthreads();
    return r;
}

// ---------------- K2: mask pass: bitpack + per-patch sums ----------------
__global__ void k2_mask(const int* __restrict__ masks) {
    int p = blockIdx.x;             // 0..2303
    int py = p / HV_, px = p % HV_;
    int tid = threadIdx.x;          // 256
    int sums[M_];
#pragma unroll
    for (int m = 0; m < M_; m++) sums[m] = 0;

    if (tid < 196) {                // 28 rows * 7 int4-groups
        int row = tid / 7, g = tid % 7;
        int y = py * PH_ + row;
        int x = px * PH_ + g * 4;
        unsigned b0 = 0, b1 = 0, b2 = 0, b3 = 0;
#pragma unroll
        for (int m = 0; m < M_; m++) {
            int4 v = *(const int4*)(masks + ((size_t)m * H_ + y) * W_ + x);
            int q0 = (v.x != 0), q1 = (v.y != 0), q2 = (v.z != 0), q3 = (v.w != 0);
            sums[m] = q0 + q1 + q2 + q3;
            b0 |= (unsigned)q0 << m; b1 |= (unsigned)q1 << m;
            b2 |= (unsigned)q2 << m; b3 |= (unsigned)q3 << m;
        }
        *(uchar4*)(g_packed + (size_t)y * W_ + x) =
            make_uchar4((unsigned char)b0, (unsigned char)b1, (unsigned char)b2, (unsigned char)b3);
    }

    __shared__ int ssum[8 * M_];
    int lane = tid & 31, w = tid >> 5;
#pragma unroll
    for (int m = 0; m < M_; m++) {
        int v = sums[m];
#pragma unroll
        for (int o = 16; o; o >>= 1) v += __shfl_down_sync(0xffffffffu, v, o);
        if (lane == 0) ssum[w * M_ + m] = v;
    }
    __syncthreads();
    if (tid < M_) {
        int t = 0;
#pragma unroll
        for (int ww = 0; ww < 8; ww++) t += ssum[ww * M_ + tid];
        g_patchsum[tid * N_ + p] = t;
    }
}

// ---------------- K2b: per-mask soft2d / logsoft / scalars ----------------
__global__ void k2b_scalars() {
    int m = blockIdx.x;
    int tid = threadIdx.x;  // 256
    __shared__ float sm[32];
    float c = 0.f, ss = 0.f, sx = 0.f, sy = 0.f;
    for (int p = tid; p < N_; p += 256) {
        int ps = g_patchsum[m * N_ + p];
        float cov = (float)ps * (1.f / 784.f);
        float soft = 1.f / (1.f + expf(-50.f * (cov - 0.3f)));
        g_soft2d[m * N_ + p] = soft;
        g_logsoft[m * N_ + p] = logf(fmaxf(soft, 1e-8f));
        c += (float)ps;
        ss += soft;
        sx += soft * (float)(p % HV_);
        sy += soft * (float)(p / HV_);
    }
    c  = blockSum(c, sm);
    ss = blockSum(ss, sm);
    sx = blockSum(sx, sm);
    sy = blockSum(sy, sm);
    if (tid == 0) {
        float soft_sum = ss + 1e-8f;
        float cx = sx / (soft_sum * (float)HV_);
        float cy = sy / (soft_sum * (float)HV_);
        g_msc[m * 8 + 0] = c;
        g_msc[m * 8 + 1] = cx;
        g_msc[m * 8 + 2] = cy;
        g_msc[m * 8 + 3] = cx * (float)(W_ - 1);
        g_msc[m * 8 + 4] = cy * (float)(H_ - 1);
    }
}

// ---------------- K3: depth row partials (predicated f32x2 adds) ----------------
__global__ void k3_depth(const float* __restrict__ depth) {
    int row = blockIdx.x, b = blockIdx.y;
    int tid = threadIdx.x;  // 256
    unsigned long long acc[M_];
#pragma unroll
    for (int m = 0; m < M_; m++) acc[m] = 0ull;

    const float4* dr = (const float4*)(depth + ((size_t)b * H_ + row) * W_);
    const uchar4* pr = (const uchar4*)(g_packed + (size_t)row * W_);

    for (int g = tid; g < W_ / 4; g += 256) {
        float4 d4 = dr[g];
        uchar4 p4 = pr[g];
        unsigned pb[4] = {p4.x, p4.y, p4.z, p4.w};
        float dv[4] = {d4.x, d4.y, d4.z, d4.w};
#pragma unroll
        for (int k = 0; k < 4; k++) {
            float d = dv[k];
            float dd = d * d;
            unsigned long long ddd;
            asm("mov.b64 %0, {%1, %2};" : "=l"(ddd)
                : "r"(__float_as_uint(d)), "r"(__float_as_uint(dd)));
            unsigned pbk = pb[k];
#pragma unroll
            for (int m = 0; m < M_; m++) {
                asm volatile(
                    "{ .reg .pred p; setp.ne.u32 p, %1, 0;\n\t"
                    "  @p add.rn.f32x2 %0, %0, %2; }"
                    : "+l"(acc[m]) : "r"(pbk & (1u << m)), "l"(ddd));
            }
        }
    }

    // unpack & reduce 16 values across block
    float vals[16];
#pragma unroll
    for (int m = 0; m < M_; m++) {
        unsigned lo, hi;
        asm("mov.b64 {%0, %1}, %2;" : "=r"(lo), "=r"(hi) : "l"(acc[m]));
        vals[m]     = __uint_as_float(lo);   // sum d
        vals[m + 8] = __uint_as_float(hi);   // sum d^2
    }
    __shared__ float sred[8 * 16];
    int lane = tid & 31, w = tid >> 5;
#pragma unroll
    for (int i = 0; i < 16; i++) {
        float v = vals[i];
#pragma unroll
        for (int o = 16; o; o >>= 1) v += __shfl_down_sync(0xffffffffu, v, o);
        if (lane == 0) sred[w * 16 + i] = v;
    }
    __syncthreads();
    if (tid < 16) {
        float t = 0.f;
#pragma unroll
        for (int ww = 0; ww < 8; ww++) t += sred[ww * 16 + tid];
        if (tid < 8) g_rowd[((size_t)tid * B_ + b) * H_ + row] = t;
        else         g_rowd2[((size_t)(tid - 8) * B_ + b) * H_ + row] = t;
    }
}

// ---------------- K5: fused scores + partial softmax + weighted sum ----------------
// grid (NCHUNK, B), 256 threads. Single pass over tokens (re-reads hit L1/L2).
__global__ void k5_fused(const float* __restrict__ tok, const float* __restrict__ gw) {
    int c = blockIdx.x, b = blockIdx.y;
    int tid = threadIdx.x;
    int lane = tid & 31, w = tid >> 5;          // 8 warps
    __shared__ float s_gw[D_];
    __shared__ float s_sc[CHUNK_N];
    __shared__ float s_e[M_][CHUNK_N];
    __shared__ float s_lm[M_], s_ls[M_];

    // load gate weights to shared
    {
        float4 v = ((const float4*)gw)[tid];
        ((float4*)s_gw)[tid] = v;
    }
    __syncthreads();

    const float* tbase = tok + ((size_t)b * N_ + (size_t)c * CHUNK_N) * D_;

    // Phase A: warp w computes dots for tokens j = w + 8*i
#pragma unroll
    for (int i = 0; i < CHUNK_N / 8; i++) {
        int j = w + 8 * i;
        const float4* tr = (const float4*)(tbase + (size_t)j * D_);
        const float4* gr = (const float4*)s_gw;
        float acc = 0.f;
#pragma unroll
        for (int it = 0; it < 8; it++) {
            float4 a = tr[lane + it * 32];
            float4 g = gr[lane + it * 32];
            acc += a.x * g.x + a.y * g.y + a.z * g.z + a.w * g.w;
        }
#pragma unroll
        for (int o = 16; o; o >>= 1) acc += __shfl_down_sync(0xffffffffu, acc, o);
        if (lane == 0) s_sc[j] = acc;
    }
    __syncthreads();

    // Phase B: warp m computes local max / exp / sum for its mask
    {
        int m = w;
        const float* ls = g_logsoft + m * N_ + c * CHUNK_N;
        float v0 = s_sc[lane]      + ls[lane];
        float v1 = s_sc[lane + 32] + ls[lane + 32];
        float mx = fmaxf(v0, v1);
#pragma unroll
        for (int o = 16; o; o >>= 1) mx = fmaxf(mx, __shfl_xor_sync(0xffffffffu, mx, o));
        float e0 = expf(v0 - mx), e1 = expf(v1 - mx);
        s_e[m][lane] = e0;
        s_e[m][lane + 32] = e1;
        float s = e0 + e1;
#pragma unroll
        for (int o = 16; o; o >>= 1) s += __shfl_xor_sync(0xffffffffu, s, o);
        if (lane == 0) { s_lm[m] = mx; s_ls[m] = s; }
    }
    __syncthreads();

    // Phase C: weighted accumulation, thread owns d-slice [tid*4, tid*4+4)
    float4 acc[M_];
#pragma unroll
    for (int m = 0; m < M_; m++) acc[m] = make_float4(0.f, 0.f, 0.f, 0.f);

    const float4* tp = (const float4*)tbase + tid;
#pragma unroll 2
    for (int j = 0; j < CHUNK_N; j++) {
        float4 t = tp[(size_t)j * (D_ / 4)];
#pragma unroll
        for (int m = 0; m < M_; m++) {
            float e = s_e[m][j];
            acc[m].x = fmaf(e, t.x, acc[m].x);
            acc[m].y = fmaf(e, t.y, acc[m].y);
            acc[m].z = fmaf(e, t.z, acc[m].z);
            acc[m].w = fmaf(e, t.w, acc[m].w);
        }
    }
#pragma unroll
    for (int m = 0; m < M_; m++) {
        ((float4*)&g_partial[(((size_t)c * M_ + m) * B_ + b) * D_])[tid] = acc[m];
    }
    if (tid < M_) {
        int idx = (c * M_ + tid) * B_ + b;
        g_locmax[idx] = s_lm[tid];
        g_locsum[idx] = s_ls[tid];
    }
}

// ---------------- K6: combine softmax partials -> rgb out ----------------
__global__ void k6_combine(float* __restrict__ out) {
    int mb = blockIdx.x;            // m*B + b
    int m = mb / B_, b = mb % B_;
    int tid = threadIdx.x;          // 256
    __shared__ float s_scale[NCHUNK];
    __shared__ float s_invS;
    if (tid == 0) {
        float MX = -1e30f;
#pragma unroll
        for (int c = 0; c < NCHUNK; c++)
            MX = fmaxf(MX, g_locmax[(c * M_ + m) * B_ + b]);
        float S = 0.f;
#pragma unroll
        for (int c = 0; c < NCHUNK; c++) {
            float sc = expf(g_locmax[(c * M_ + m) * B_ + b] - MX);
            s_scale[c] = sc;
            S += sc * g_locsum[(c * M_ + m) * B_ + b];
        }
        s_invS = 1.f / S;
    }
    __syncthreads();
    float4 a = make_float4(0.f, 0.f, 0.f, 0.f);
#pragma unroll
    for (int c = 0; c < NCHUNK; c++) {
        float sc = s_scale[c];
        float4 p = ((const float4*)&g_partial[(((size_t)c * M_ + m) * B_ + b) * D_])[tid];
        a.x = fmaf(sc, p.x, a.x);
        a.y = fmaf(sc, p.y, a.y);
        a.z = fmaf(sc, p.z, a.z);
        a.w = fmaf(sc, p.w, a.w);
    }
    float inv = s_invS;
    a.x *= inv; a.y *= inv; a.z *= inv; a.w *= inv;
    ((float4*)&out[((size_t)m * B_ + b) * D_])[tid] = a;
}

// ---------------- bilinear helpers ----------------
__device__ __forceinline__ float bilin_border(const float* img, float x, float y) {
    x = fminf(fmaxf(x, 0.f), (float)(W_ - 1));
    y = fminf(fmaxf(y, 0.f), (float)(H_ - 1));
    float x0f = floorf(x), y0f = floorf(y);
    float wx = x - x0f, wy = y - y0f;
    int x0 = (int)x0f, y0 = (int)y0f;
    int x1 = min(x0 + 1, W_ - 1), y1 = min(y0 + 1, H_ - 1);
    return img[y0 * W_ + x0] * (1.f - wx) * (1.f - wy)
         + img[y0 * W_ + x1] * wx * (1.f - wy)
         + img[y1 * W_ + x0] * (1.f - wx) * wy
         + img[y1 * W_ + x1] * wx * wy;
}

__device__ __forceinline__ float tap48(const float* img, int yy, int xx, float w) {
    if (xx >= 0 && xx < HV_ && yy >= 0 && yy < HV_) return img[yy * HV_ + xx] * w;
    return 0.f;
}

__device__ __forceinline__ float bilin_zeros48(const float* img, float x, float y) {
    float x0f = floorf(x), y0f = floorf(y);
    float wx = x - x0f, wy = y - y0f;
    int x0 = (int)x0f, y0 = (int)y0f;
    float v = tap48(img, y0, x0, (1.f - wx) * (1.f - wy));
    v += tap48(img, y0, x0 + 1, wx * (1.f - wy));
    v += tap48(img, y0 + 1, x0, (1.f - wx) * wy);
    v += tap48(img, y0 + 1, x0 + 1, wx * wy);
    return v;
}

// ---------------- K7: rays + stats + GEMV + layernorm -> dep output ----------------
__global__ void k7_dep(const float* __restrict__ depth,
                       const float* __restrict__ dw, const float* __restrict__ db,
                       const float* __restrict__ gamma, const float* __restrict__ beta,
                       float* __restrict__ out) {
    int b = blockIdx.x, m = blockIdx.y;
    int tid = threadIdx.x;  // 512
    __shared__ float sm[32];
    __shared__ float s_stats[28];
    __shared__ float s_ds[NRAYS * NSAMP];
    __shared__ float s_sw[NRAYS * NSAMP];

    float a = 0.f, a2 = 0.f;
    for (int r = tid; r < H_; r += 512) {
        a  += g_rowd[((size_t)m * B_ + b) * H_ + r];
        a2 += g_rowd2[((size_t)m * B_ + b) * H_ + r];
    }
    float sum_d  = blockSum(a, sm);
    float sum_d2 = blockSum(a2, sm);

    float count = g_msc[m * 8 + 0];
    float cx    = g_msc[m * 8 + 1];
    float cy    = g_msc[m * 8 + 2];
    float cxp   = g_msc[m * 8 + 3];
    float cyp   = g_msc[m * 8 + 4];

    float mean_d = sum_d / fmaxf(count, 1.f);
    float var = (sum_d2 - count * mean_d * mean_d) / fmaxf(count - 1.f, 1.f);
    float std_d = (count > 1.f) ? sqrtf(fmaxf(var, 0.f)) : 0.f;

    if (tid < NRAYS * NSAMP) {
        int r = tid / NSAMP, s = tid % NSAMP;
        double ang = (2.0 * 3.14159265358979323846 / (double)NRAYS) * (double)r;
        float ca = (float)cos(ang), sa = (float)sin(ang);
        float tv = (float)(((double)(W_ < H_ ? W_ : H_) * 0.45 / (double)(NSAMP - 1)) * (double)s);
        float x = cxp + ca * tv;
        float y = cyp + sa * tv;
        const float* dm = depth + (size_t)b * H_ * W_;
        s_ds[tid] = bilin_border(dm, x, y);
        float xp = x / (float)(W_ - 1) * (float)(HV_ - 1);
        float yp = y / (float)(H_ - 1) * (float)(HV_ - 1);
        float sw = bilin_zeros48(g_soft2d + m * N_, xp, yp);
        s_sw[tid] = fmaxf(sw, 1e-6f);
    }
    __syncthreads();

    if (tid < NRAYS) {
        float ws = 0.f, pr = 0.f;
#pragma unroll
        for (int s = 0; s < NSAMP; s++) {
            ws += s_sw[tid * NSAMP + s];
            pr += s_ds[tid * NSAMP + s] * s_sw[tid * NSAMP + s];
        }
        float ok = (count > 0.f) ? 1.f : 0.f;
        s_stats[4 + tid] = (pr / ws) * ok;
    }
    if (tid == 0) {
        float ok = (count > 0.f) ? 1.f : 0.f;
        s_stats[0] = mean_d * ok;
        s_stats[1] = std_d * ok;
        s_stats[2] = cx * ok;
        s_stats[3] = cy * ok;
    }
    __syncthreads();

    float h0 = db[tid], h1 = db[tid + 512];
#pragma unroll
    for (int k = 0; k < 28; k++) {
        float st = s_stats[k];
        h0 = fmaf(st, dw[k * D_ + tid], h0);
        h1 = fmaf(st, dw[k * D_ + tid + 512], h1);
    }
    float mu = blockSum(h0 + h1, sm) * (1.f / (float)D_);
    float e0 = h0 - mu, e1 = h1 - mu;
    float v2 = blockSum(e0 * e0 + e1 * e1, sm) * (1.f / (float)D_);
    float inv = rsqrtf(v2 + 1e-5f);
    size_t off = (size_t)(M_ * B_ * D_) + ((size_t)m * B_ + b) * D_;
    out[off + tid]       = e0 * inv * gamma[tid] + beta[tid];
    out[off + tid + 512] = e1 * inv * gamma[tid + 512] + beta[tid + 512];
}

// ---------------- launch ----------------
extern "C" void kernel_launch(void* const* d_in, const int* in_sizes, int n_in,
                              void* d_out, int out_size) {
    const float* tok   = (const float*)d_in[0];
    const float* depth = (const float*)d_in[1];
    const int*   masks = (const int*)d_in[2];
    const float* gw    = (const float*)d_in[3];
    const float* dw    = (const float*)d_in[4];
    const float* db    = (const float*)d_in[5];
    const float* gamma = (const float*)d_in[6];
    const float* beta  = (const float*)d_in[7];
    float* out = (float*)d_out;

    k2_mask<<<N_, 256>>>(masks);
    k2b_scalars<<<M_, 256>>>();
    k3_depth<<<dim3(H_, B_), 256>>>(depth);
    k5_fused<<<dim3(NCHUNK, B_), 256>>>(tok, gw);
    k6_combine<<<M_ * B_, 256>>>(out);
    k7_dep<<<dim3(B_, M_), 512>>>(depth, dw, db, gamma, beta, out);
}

// round 3
// speedup vs baseline: 1.6184x; 1.2920x over previous
#include <cuda_runtime.h>
#include <math.h>

#define B_ 16
#define N_ 2304
#define D_ 1024
#define H_ 1344
#define W_ 1344
#define M_ 8
#define HV_ 48
#define PH_ 28
#define NRAYS 24
#define NSAMP 20

#define NCH2 9            // chunks for rgb pass
#define CH2 256           // tokens per chunk
#define SUBT 16           // tokens per subtile
#define NSUB 16           // subtiles per chunk

#define RG_ 168           // row groups (H/8)
#define ROWS_PER_BLK 8

// ---------------- scratch ----------------
__device__ unsigned char g_packed[H_ * W_];
__device__ int           g_patchsum[M_ * N_];
__device__ float         g_soft2d[M_ * N_];
__device__ float         g_logsoft[M_ * N_];
__device__ float         g_msc[M_ * 8];
__device__ float         g_rowd[M_ * B_ * RG_];
__device__ float         g_rowd2[M_ * B_ * RG_];
__device__ float         g_partial[NCH2 * M_ * B_ * D_];   // 4.7 MB
__device__ float         g_locmax[NCH2 * M_ * B_];
__device__ float         g_locsum[NCH2 * M_ * B_];

// ---------------- helpers ----------------
__device__ __forceinline__ float blockSum(float v, float* sm) {
    int lane = threadIdx.x & 31, w = threadIdx.x >> 5;
    int nw = blockDim.x >> 5;
#pragma unroll
    for (int o = 16; o; o >>= 1) v += __shfl_down_sync(0xffffffffu, v, o);
    if (lane == 0) sm[w] = v;
    __syncthreads();
    if (w == 0) {
        v = (lane < nw) ? sm[lane] : 0.f;
#pragma unroll
        for (int o = 16; o; o >>= 1) v += __shfl_down_sync(0xffffffffu, v, o);
        if (lane == 0) sm[0] = v;
    }
    __syncthreads();
    float r = sm[0];
    __syncthreads();
    return r;
}

#define CP_ASYNC16(dst_smem_u32, src) \
    asm volatile("cp.async.cg.shared.global [%0], [%1], 16;" :: "r"(dst_smem_u32), "l"(src))
#define CP_COMMIT() asm volatile("cp.async.commit_group;")
#define CP_WAIT1() asm volatile("cp.async.wait_group 1;")
#define CP_WAIT0() asm volatile("cp.async.wait_group 0;")

// ---------------- K2: mask bitpack + per-patch sums ----------------
__global__ void k2_mask(const int* __restrict__ masks) {
    int p = blockIdx.x;
    int py = p / HV_, px = p % HV_;
    int tid = threadIdx.x;          // 256
    int sums[M_];
#pragma unroll
    for (int m = 0; m < M_; m++) sums[m] = 0;

    if (tid < 196) {
        int row = tid / 7, g = tid % 7;
        int y = py * PH_ + row;
        int x = px * PH_ + g * 4;
        unsigned b0 = 0, b1 = 0, b2 = 0, b3 = 0;
#pragma unroll
        for (int m = 0; m < M_; m++) {
            int4 v = *(const int4*)(masks + ((size_t)m * H_ + y) * W_ + x);
            int q0 = (v.x != 0), q1 = (v.y != 0), q2 = (v.z != 0), q3 = (v.w != 0);
            sums[m] = q0 + q1 + q2 + q3;
            b0 |= (unsigned)q0 << m; b1 |= (unsigned)q1 << m;
            b2 |= (unsigned)q2 << m; b3 |= (unsigned)q3 << m;
        }
        *(uchar4*)(g_packed + (size_t)y * W_ + x) =
            make_uchar4((unsigned char)b0, (unsigned char)b1, (unsigned char)b2, (unsigned char)b3);
    }

    __shared__ int ssum[8 * M_];
    int lane = tid & 31, w = tid >> 5;
#pragma unroll
    for (int m = 0; m < M_; m++) {
        int v = sums[m];
#pragma unroll
        for (int o = 16; o; o >>= 1) v += __shfl_down_sync(0xffffffffu, v, o);
        if (lane == 0) ssum[w * M_ + m] = v;
    }
    __syncthreads();
    if (tid < M_) {
        int t = 0;
#pragma unroll
        for (int ww = 0; ww < 8; ww++) t += ssum[ww * M_ + tid];
        g_patchsum[tid * N_ + p] = t;
    }
}

// ---------------- K2b: soft2d / logsoft / per-mask scalars ----------------
__global__ void k2b_scalars() {
    int m = blockIdx.x;
    int tid = threadIdx.x;  // 256
    __shared__ float sm[32];
    float c = 0.f, ss = 0.f, sx = 0.f, sy = 0.f;
    for (int p = tid; p < N_; p += 256) {
        int ps = g_patchsum[m * N_ + p];
        float cov = (float)ps * (1.f / 784.f);
        float soft = 1.f / (1.f + expf(-50.f * (cov - 0.3f)));
        g_soft2d[m * N_ + p] = soft;
        g_logsoft[m * N_ + p] = logf(fmaxf(soft, 1e-8f));
        c += (float)ps;
        ss += soft;
        sx += soft * (float)(p % HV_);
        sy += soft * (float)(p / HV_);
    }
    c  = blockSum(c, sm);
    ss = blockSum(ss, sm);
    sx = blockSum(sx, sm);
    sy = blockSum(sy, sm);
    if (tid == 0) {
        float soft_sum = ss + 1e-8f;
        float cx = sx / (soft_sum * (float)HV_);
        float cy = sy / (soft_sum * (float)HV_);
        g_msc[m * 8 + 0] = c;
        g_msc[m * 8 + 1] = cx;
        g_msc[m * 8 + 2] = cy;
        g_msc[m * 8 + 3] = cx * (float)(W_ - 1);
        g_msc[m * 8 + 4] = cy * (float)(H_ - 1);
    }
}

// ---------------- K3: depth partials, 8 rows x 2 batches per block ----------------
__global__ void __launch_bounds__(256) k3_depth(const float* __restrict__ depth) {
    int rg = blockIdx.x;            // 0..167
    int bg = blockIdx.y;            // 0..7  (b = 2*bg, 2*bg+1)
    int tid = threadIdx.x;          // 256
    int b0 = bg * 2, b1 = b0 + 1;
    int row0 = rg * ROWS_PER_BLK;

    unsigned long long acc[16];     // [b2*8 + m], (sum_d, sum_d2) packed f32x2
#pragma unroll
    for (int i = 0; i < 16; i++) acc[i] = 0ull;

    const int NG = ROWS_PER_BLK * (W_ / 4);   // 2688 float4-groups
    for (int idx = tid; idx < NG; idx += 256) {
        int r = idx / (W_ / 4);
        int g = idx - r * (W_ / 4);
        int row = row0 + r;
        uchar4 p4 = ((const uchar4*)(g_packed + (size_t)row * W_))[g];
        float4 da = ((const float4*)(depth + ((size_t)b0 * H_ + row) * W_))[g];
        float4 db = ((const float4*)(depth + ((size_t)b1 * H_ + row) * W_))[g];
        unsigned pb[4] = {p4.x, p4.y, p4.z, p4.w};
        float va[4] = {da.x, da.y, da.z, da.w};
        float vb[4] = {db.x, db.y, db.z, db.w};
#pragma unroll
        for (int k = 0; k < 4; k++) {
            float dA = va[k], dB = vb[k];
            unsigned long long ddA, ddB;
            asm("mov.b64 %0, {%1, %2};" : "=l"(ddA)
                : "r"(__float_as_uint(dA)), "r"(__float_as_uint(dA * dA)));
            asm("mov.b64 %0, {%1, %2};" : "=l"(ddB)
                : "r"(__float_as_uint(dB)), "r"(__float_as_uint(dB * dB)));
            unsigned pbk = pb[k];
#pragma unroll
            for (int m = 0; m < M_; m++) {
                asm volatile(
                    "{ .reg .pred p; setp.ne.u32 p, %2, 0;\n\t"
                    "  @p add.rn.f32x2 %0, %0, %3;\n\t"
                    "  @p add.rn.f32x2 %1, %1, %4; }"
                    : "+l"(acc[m]), "+l"(acc[8 + m])
                    : "r"(pbk & (1u << m)), "l"(ddA), "l"(ddB));
            }
        }
    }

    // warp tree on 16 packed accumulators, then cross-warp via smem
    __shared__ unsigned long long sred[8][16];
    int lane = tid & 31, w = tid >> 5;
#pragma unroll
    for (int i = 0; i < 16; i++) {
        unsigned long long v = acc[i];
#pragma unroll
        for (int o = 16; o; o >>= 1) {
            unsigned long long u = __shfl_down_sync(0xffffffffu, v, o);
            asm("add.rn.f32x2 %0, %0, %1;" : "+l"(v) : "l"(u));
        }
        if (lane == 0) sred[w][i] = v;
    }
    __syncthreads();
    if (tid < 16) {
        float sd = 0.f, sd2 = 0.f;
#pragma unroll
        for (int ww = 0; ww < 8; ww++) {
            unsigned lo, hi;
            asm("mov.b64 {%0, %1}, %2;" : "=r"(lo), "=r"(hi) : "l"(sred[ww][tid]));
            sd  += __uint_as_float(lo);
            sd2 += __uint_as_float(hi);
        }
        int b = b0 + (tid >> 3);
        int m = tid & 7;
        g_rowd[((size_t)m * B_ + b) * RG_ + rg]  = sd;
        g_rowd2[((size_t)m * B_ + b) * RG_ + rg] = sd2;
    }
}

// ---------------- K5: persistent fused scores + online softmax + weighted sum ----------------
// grid (NCH2, B), 512 threads, dynamic smem: [gw 1024][buf0 16K][buf1 16K][sc 16][e 16*8][scale 8]
__global__ void __launch_bounds__(512) k5_fused(const float* __restrict__ tok,
                                                const float* __restrict__ gw) {
    extern __shared__ float smem[];
    float* s_gw    = smem;                 // 1024
    float* s_buf   = smem + 1024;          // 2 x 16384
    float* s_sc    = smem + 1024 + 2 * 16384;      // 16
    float* s_e     = s_sc + 16;            // [SUBT][8]
    float* s_scale = s_e + SUBT * 8;       // 8

    int c = blockIdx.x, b = blockIdx.y;
    int tid = threadIdx.x;
    int lane = tid & 31, w = tid >> 5;     // 16 warps
    const float* gtok = tok + ((size_t)b * N_ + (size_t)c * CH2) * D_;

    // gate weights to smem
    ((float2*)s_gw)[tid] = ((const float2*)gw)[tid];

    // prologue: async copy subtile 0
    {
        unsigned dst = (unsigned)__cvta_generic_to_shared(s_buf) + tid * 16;
#pragma unroll
        for (int i = 0; i < 8; i++)
            CP_ASYNC16(dst + i * 512 * 16, (const float4*)gtok + tid + i * 512);
        CP_COMMIT();
    }

    float2 acc2[M_];
#pragma unroll
    for (int m = 0; m < M_; m++) acc2[m] = make_float2(0.f, 0.f);
    float rm = -3.0e38f, rs = 0.f;         // per-warp online softmax state (warps 0..7)

    for (int t = 0; t < NSUB; t++) {
        float* buf = s_buf + (t & 1) * 16384;
        if (t + 1 < NSUB) {
            float* nbuf = s_buf + ((t + 1) & 1) * 16384;
            unsigned dst = (unsigned)__cvta_generic_to_shared(nbuf) + tid * 16;
            const float4* src = (const float4*)(gtok + (size_t)(t + 1) * SUBT * D_) + tid;
#pragma unroll
            for (int i = 0; i < 8; i++)
                CP_ASYNC16(dst + i * 512 * 16, src + i * 512);
            CP_COMMIT();
            CP_WAIT1();
        } else {
            CP_WAIT0();
        }
        __syncthreads();

        // dots: warp w owns token w (16 warps, 16 tokens)
        {
            const float4* tp = (const float4*)(buf + (size_t)w * D_);
            const float4* gp = (const float4*)s_gw;
            float acc = 0.f;
#pragma unroll
            for (int it = 0; it < 8; it++) {
                float4 a = tp[lane + it * 32];
                float4 g = gp[lane + it * 32];
                acc += a.x * g.x + a.y * g.y + a.z * g.z + a.w * g.w;
            }
#pragma unroll
            for (int o = 16; o; o >>= 1) acc += __shfl_down_sync(0xffffffffu, acc, o);
            if (lane == 0) s_sc[w] = acc;
        }
        __syncthreads();

        // online softmax: warp m (<8), lanes 0..15 = tokens
        if (w < 8) {
            int m = w;
            float v = -3.0e38f;
            if (lane < SUBT)
                v = s_sc[lane] + g_logsoft[m * N_ + c * CH2 + t * SUBT + lane];
            float mx = v;
#pragma unroll
            for (int o = 16; o; o >>= 1) mx = fmaxf(mx, __shfl_xor_sync(0xffffffffu, mx, o));
            float nm = fmaxf(rm, mx);
            float sc = expf(rm - nm);
            float e = (lane < SUBT) ? expf(v - nm) : 0.f;
            if (lane < SUBT) s_e[lane * 8 + m] = e;
            float se = e;
#pragma unroll
            for (int o = 16; o; o >>= 1) se += __shfl_xor_sync(0xffffffffu, se, o);
            rs = rs * sc + se;
            rm = nm;
            if (lane == 0) s_scale[m] = sc;
        }
        __syncthreads();

        // accumulate: thread owns d-pair [2*tid, 2*tid+1]
        {
            float sc0 = s_scale[0], sc1 = s_scale[1], sc2 = s_scale[2], sc3 = s_scale[3];
            float sc4 = s_scale[4], sc5 = s_scale[5], sc6 = s_scale[6], sc7 = s_scale[7];
            acc2[0].x *= sc0; acc2[0].y *= sc0;
            acc2[1].x *= sc1; acc2[1].y *= sc1;
            acc2[2].x *= sc2; acc2[2].y *= sc2;
            acc2[3].x *= sc3; acc2[3].y *= sc3;
            acc2[4].x *= sc4; acc2[4].y *= sc4;
            acc2[5].x *= sc5; acc2[5].y *= sc5;
            acc2[6].x *= sc6; acc2[6].y *= sc6;
            acc2[7].x *= sc7; acc2[7].y *= sc7;
#pragma unroll
            for (int j = 0; j < SUBT; j++) {
                float2 tv = *(const float2*)(buf + (size_t)j * D_ + tid * 2);
                float4 e0 = *(const float4*)(s_e + j * 8);
                float4 e1 = *(const float4*)(s_e + j * 8 + 4);
                acc2[0].x = fmaf(e0.x, tv.x, acc2[0].x); acc2[0].y = fmaf(e0.x, tv.y, acc2[0].y);
                acc2[1].x = fmaf(e0.y, tv.x, acc2[1].x); acc2[1].y = fmaf(e0.y, tv.y, acc2[1].y);
                acc2[2].x = fmaf(e0.z, tv.x, acc2[2].x); acc2[2].y = fmaf(e0.z, tv.y, acc2[2].y);
                acc2[3].x = fmaf(e0.w, tv.x, acc2[3].x); acc2[3].y = fmaf(e0.w, tv.y, acc2[3].y);
                acc2[4].x = fmaf(e1.x, tv.x, acc2[4].x); acc2[4].y = fmaf(e1.x, tv.y, acc2[4].y);
                acc2[5].x = fmaf(e1.y, tv.x, acc2[5].x); acc2[5].y = fmaf(e1.y, tv.y, acc2[5].y);
                acc2[6].x = fmaf(e1.z, tv.x, acc2[6].x); acc2[6].y = fmaf(e1.z, tv.y, acc2[6].y);
                acc2[7].x = fmaf(e1.w, tv.x, acc2[7].x); acc2[7].y = fmaf(e1.w, tv.y, acc2[7].y);
            }
        }
        __syncthreads();
    }

    // write partials
#pragma unroll
    for (int m = 0; m < M_; m++)
        *(float2*)&g_partial[(((size_t)c * M_ + m) * B_ + b) * D_ + tid * 2] = acc2[m];
    if (w < 8 && lane == 0) {
        int idx = (c * M_ + w) * B_ + b;
        g_locmax[idx] = rm;
        g_locsum[idx] = rs;
    }
}

// ---------------- K6: combine partials -> rgb out ----------------
__global__ void k6_combine(float* __restrict__ out) {
    int mb = blockIdx.x;            // m*B + b
    int m = mb / B_, b = mb % B_;
    int tid = threadIdx.x;          // 256
    __shared__ float s_scale[NCH2];
    __shared__ float s_invS;
    if (tid == 0) {
        float MX = -1e30f;
#pragma unroll
        for (int c = 0; c < NCH2; c++)
            MX = fmaxf(MX, g_locmax[(c * M_ + m) * B_ + b]);
        float S = 0.f;
#pragma unroll
        for (int c = 0; c < NCH2; c++) {
            float sc = expf(g_locmax[(c * M_ + m) * B_ + b] - MX);
            s_scale[c] = sc;
            S += sc * g_locsum[(c * M_ + m) * B_ + b];
        }
        s_invS = 1.f / S;
    }
    __syncthreads();
    float4 a = make_float4(0.f, 0.f, 0.f, 0.f);
#pragma unroll
    for (int c = 0; c < NCH2; c++) {
        float sc = s_scale[c];
        float4 p = ((const float4*)&g_partial[(((size_t)c * M_ + m) * B_ + b) * D_])[tid];
        a.x = fmaf(sc, p.x, a.x);
        a.y = fmaf(sc, p.y, a.y);
        a.z = fmaf(sc, p.z, a.z);
        a.w = fmaf(sc, p.w, a.w);
    }
    float inv = s_invS;
    a.x *= inv; a.y *= inv; a.z *= inv; a.w *= inv;
    ((float4*)&out[((size_t)m * B_ + b) * D_])[tid] = a;
}

// ---------------- bilinear helpers ----------------
__device__ __forceinline__ float bilin_border(const float* img, float x, float y) {
    x = fminf(fmaxf(x, 0.f), (float)(W_ - 1));
    y = fminf(fmaxf(y, 0.f), (float)(H_ - 1));
    float x0f = floorf(x), y0f = floorf(y);
    float wx = x - x0f, wy = y - y0f;
    int x0 = (int)x0f, y0 = (int)y0f;
    int x1 = min(x0 + 1, W_ - 1), y1 = min(y0 + 1, H_ - 1);
    return img[y0 * W_ + x0] * (1.f - wx) * (1.f - wy)
         + img[y0 * W_ + x1] * wx * (1.f - wy)
         + img[y1 * W_ + x0] * (1.f - wx) * wy
         + img[y1 * W_ + x1] * wx * wy;
}

__device__ __forceinline__ float tap48(const float* img, int yy, int xx, float w) {
    if (xx >= 0 && xx < HV_ && yy >= 0 && yy < HV_) return img[yy * HV_ + xx] * w;
    return 0.f;
}

__device__ __forceinline__ float bilin_zeros48(const float* img, float x, float y) {
    float x0f = floorf(x), y0f = floorf(y);
    float wx = x - x0f, wy = y - y0f;
    int x0 = (int)x0f, y0 = (int)y0f;
    float v = tap48(img, y0, x0, (1.f - wx) * (1.f - wy));
    v += tap48(img, y0, x0 + 1, wx * (1.f - wy));
    v += tap48(img, y0 + 1, x0, (1.f - wx) * wy);
    v += tap48(img, y0 + 1, x0 + 1, wx * wy);
    return v;
}

// ---------------- K7: rays + stats + GEMV + layernorm ----------------
__global__ void k7_dep(const float* __restrict__ depth,
                       const float* __restrict__ dw, const float* __restrict__ db,
                       const float* __restrict__ gamma, const float* __restrict__ beta,
                       float* __restrict__ out) {
    int b = blockIdx.x, m = blockIdx.y;
    int tid = threadIdx.x;  // 512
    __shared__ float sm[32];
    __shared__ float s_stats[28];
    __shared__ float s_ds[NRAYS * NSAMP];
    __shared__ float s_sw[NRAYS * NSAMP];

    float a = 0.f, a2 = 0.f;
    if (tid < RG_) {
        a  = g_rowd[((size_t)m * B_ + b) * RG_ + tid];
        a2 = g_rowd2[((size_t)m * B_ + b) * RG_ + tid];
    }
    float sum_d  = blockSum(a, sm);
    float sum_d2 = blockSum(a2, sm);

    float count = g_msc[m * 8 + 0];
    float cx    = g_msc[m * 8 + 1];
    float cy    = g_msc[m * 8 + 2];
    float cxp   = g_msc[m * 8 + 3];
    float cyp   = g_msc[m * 8 + 4];

    float mean_d = sum_d / fmaxf(count, 1.f);
    float var = (sum_d2 - count * mean_d * mean_d) / fmaxf(count - 1.f, 1.f);
    float std_d = (count > 1.f) ? sqrtf(fmaxf(var, 0.f)) : 0.f;

    if (tid < NRAYS * NSAMP) {
        int r = tid / NSAMP, s = tid % NSAMP;
        double ang = (2.0 * 3.14159265358979323846 / (double)NRAYS) * (double)r;
        float ca = (float)cos(ang), sa = (float)sin(ang);
        float tv = (float)(((double)(W_ < H_ ? W_ : H_) * 0.45 / (double)(NSAMP - 1)) * (double)s);
        float x = cxp + ca * tv;
        float y = cyp + sa * tv;
        const float* dm = depth + (size_t)b * H_ * W_;
        s_ds[tid] = bilin_border(dm, x, y);
        float xp = x / (float)(W_ - 1) * (float)(HV_ - 1);
        float yp = y / (float)(H_ - 1) * (float)(HV_ - 1);
        float sw = bilin_zeros48(g_soft2d + m * N_, xp, yp);
        s_sw[tid] = fmaxf(sw, 1e-6f);
    }
    __syncthreads();

    if (tid < NRAYS) {
        float ws = 0.f, pr = 0.f;
#pragma unroll
        for (int s = 0; s < NSAMP; s++) {
            ws += s_sw[tid * NSAMP + s];
            pr += s_ds[tid * NSAMP + s] * s_sw[tid * NSAMP + s];
        }
        float ok = (count > 0.f) ? 1.f : 0.f;
        s_stats[4 + tid] = (pr / ws) * ok;
    }
    if (tid == 0) {
        float ok = (count > 0.f) ? 1.f : 0.f;
        s_stats[0] = mean_d * ok;
        s_stats[1] = std_d * ok;
        s_stats[2] = cx * ok;
        s_stats[3] = cy * ok;
    }
    __syncthreads();

    float h0 = db[tid], h1 = db[tid + 512];
#pragma unroll
    for (int k = 0; k < 28; k++) {
        float st = s_stats[k];
        h0 = fmaf(st, dw[k * D_ + tid], h0);
        h1 = fmaf(st, dw[k * D_ + tid + 512], h1);
    }
    float mu = blockSum(h0 + h1, sm) * (1.f / (float)D_);
    float e0 = h0 - mu, e1 = h1 - mu;
    float v2 = blockSum(e0 * e0 + e1 * e1, sm) * (1.f / (float)D_);
    float inv = rsqrtf(v2 + 1e-5f);
    size_t off = (size_t)(M_ * B_ * D_) + ((size_t)m * B_ + b) * D_;
    out[off + tid]       = e0 * inv * gamma[tid] + beta[tid];
    out[off + tid + 512] = e1 * inv * gamma[tid + 512] + beta[tid + 512];
}

// ---------------- launch ----------------
#define K5_SMEM ((1024 + 2 * 16384 + 16 + SUBT * 8 + 8) * 4)

extern "C" void kernel_launch(void* const* d_in, const int* in_sizes, int n_in,
                              void* d_out, int out_size) {
    const float* tok   = (const float*)d_in[0];
    const float* depth = (const float*)d_in[1];
    const int*   masks = (const int*)d_in[2];
    const float* gw    = (const float*)d_in[3];
    const float* dw    = (const float*)d_in[4];
    const float* db    = (const float*)d_in[5];
    const float* gamma = (const float*)d_in[6];
    const float* beta  = (const float*)d_in[7];
    float* out = (float*)d_out;

    cudaFuncSetAttribute(k5_fused, cudaFuncAttributeMaxDynamicSharedMemorySize, K5_SMEM);

    k2_mask<<<N_, 256>>>(masks);
    k2b_scalars<<<M_, 256>>>();
    k3_depth<<<dim3(RG_, B_ / 2), 256>>>(depth);
    k5_fused<<<dim3(NCH2, B_), 512, K5_SMEM>>>(tok, gw);
    k6_combine<<<M_ * B_, 256>>>(out);
    k7_dep<<<dim3(B_, M_), 512>>>(depth, dw, db, gamma, beta, out);
}